// round 2
// baseline (speedup 1.0000x reference)
#include <cuda_runtime.h>
#include <cuda_bf16.h>
#include <math.h>

#define H      256
#define HE     64
#define NB     8
#define APER   64
#define NPER   512
#define EPSF   1e-8f
#define INFM   1000000.0f
#define MU_STEP (20.0f/63.0f)
#define INV_SIG (64.0f/20.0f)   /* 1/sigma, sigma = 20/64 */

// ------------------------- scratch (device globals; no allocs) ---------------
__device__ float g_q  [512*256];
__device__ float g_qek[512*64];
__device__ float g_kvn[4096*512];
__device__ float g_af [512*256];
__device__ float g_m1 [512*512];
__device__ float g_m2 [512*512];
__device__ float g_m3 [512*256];

// ------------------------- small utils --------------------------------------
__device__ __forceinline__ float warp_reduce_sum(float v){
#pragma unroll
  for (int o=16;o>0;o>>=1) v += __shfl_xor_sync(0xffffffffu, v, o);
  return v;
}
__device__ __forceinline__ float warp_reduce_max(float v){
#pragma unroll
  for (int o=16;o>0;o>>=1) v = fmaxf(v, __shfl_xor_sync(0xffffffffu, v, o));
  return v;
}
// block of exactly 256 threads (8 warps)
__device__ __forceinline__ float block_reduce_sum(float v, float* red){
  int lane = threadIdx.x & 31, warp = threadIdx.x >> 5;
  v = warp_reduce_sum(v);
  __syncthreads();
  if (lane == 0) red[warp] = v;
  __syncthreads();
  float s = red[0]+red[1]+red[2]+red[3]+red[4]+red[5]+red[6]+red[7];
  return s;
}
__device__ __forceinline__ float block_reduce_max(float v, float* red){
  int lane = threadIdx.x & 31, warp = threadIdx.x >> 5;
  v = warp_reduce_max(v);
  __syncthreads();
  if (lane == 0) red[warp] = v;
  __syncthreads();
  float s = fmaxf(fmaxf(fmaxf(red[0],red[1]),fmaxf(red[2],red[3])),
                  fmaxf(fmaxf(red[4],red[5]),fmaxf(red[6],red[7])));
  return s;
}

// ------------------------- generic tiled GEMM -------------------------------
// C[M,N] = act( A[M,K] @ op(B) + bias )
// B_KN=false: B is (N,K) row-major with leading dim ldb (weight @ W.T form)
// B_KN=true : B is (K,N) row-major with leading dim ldb
// Requires M%64==0, N%64==0, K%16==0. 256 threads, 64x64 tile, 4x4 per thread.
template<bool B_KN, bool BIAS, bool RELU>
__global__ void gemm64(const float* __restrict__ A, int lda,
                       const float* __restrict__ B, int ldb,
                       const float* __restrict__ bias,
                       float* __restrict__ C, int ldc,
                       int M, int N, int K)
{
  __shared__ float As[16][65];
  __shared__ float Bs[16][65];
  const int tid = threadIdx.x;
  const int tx = tid & 15, ty = tid >> 4;
  const int m0 = blockIdx.y * 64, n0 = blockIdx.x * 64;
  float acc[4][4];
#pragma unroll
  for (int i=0;i<4;i++)
#pragma unroll
    for (int j=0;j<4;j++) acc[i][j] = 0.0f;

  for (int k0 = 0; k0 < K; k0 += 16) {
    {
      int k = tid & 15, m = tid >> 4;
#pragma unroll
      for (int p = 0; p < 4; p++)
        As[k][m + p*16] = A[(size_t)(m0 + m + p*16) * lda + k0 + k];
    }
    if (B_KN) {
      int n = tid & 63, kk = tid >> 6;
#pragma unroll
      for (int p = 0; p < 4; p++)
        Bs[kk + p*4][n] = B[(size_t)(k0 + kk + p*4) * ldb + n0 + n];
    } else {
      int k = tid & 15, n = tid >> 4;
#pragma unroll
      for (int p = 0; p < 4; p++)
        Bs[k][n + p*16] = B[(size_t)(n0 + n + p*16) * ldb + k0 + k];
    }
    __syncthreads();
#pragma unroll
    for (int kk = 0; kk < 16; kk++) {
      float a[4], b[4];
#pragma unroll
      for (int i=0;i<4;i++) a[i] = As[kk][ty*4+i];
#pragma unroll
      for (int j=0;j<4;j++) b[j] = Bs[kk][tx*4+j];
#pragma unroll
      for (int i=0;i<4;i++)
#pragma unroll
        for (int j=0;j<4;j++) acc[i][j] = fmaf(a[i], b[j], acc[i][j]);
    }
    __syncthreads();
  }
#pragma unroll
  for (int i=0;i<4;i++){
    int m = m0 + ty*4 + i;
#pragma unroll
    for (int j=0;j<4;j++){
      int n = n0 + tx*4 + j;
      float v = acc[i][j];
      if (BIAS) v += bias[n];
      if (RELU) v = fmaxf(v, 0.0f);
      C[(size_t)m*ldc + n] = v;
    }
  }
}

// ------------------------- fused attention + LN1 -----------------------------
// One block = 4 anchors (same batch). 256 threads.
__global__ void attn_kernel(const float* __restrict__ anchor_x,
                            const float* __restrict__ node_x,
                            const float* __restrict__ afeat,
                            const float* __restrict__ nmask,
                            const float* __restrict__ Wkv,
                            const float* __restrict__ ln1g,
                            const float* __restrict__ ln1b,
                            float* __restrict__ af_out)
{
  const int tid  = threadIdx.x;
  const int lane = tid & 31, warp = tid >> 5;
  const int a0   = blockIdx.x * 4;     // global anchor base (4 anchors/block)
  const int b    = a0 / APER;
  const int nbase = b * NPER;

  __shared__ float q_s  [4][H];
  __shared__ float qek_s[4][HE];
  __shared__ float ax_s [4][3];
  __shared__ float dist_s[4][NPER];
  __shared__ float attn_s[4][NPER];    // logits, then probabilities
  __shared__ float s_s  [4][HE];
  __shared__ float xbuf [4][H];
  __shared__ float red  [8];

  // load q / qek / anchor positions
  for (int i = tid; i < 4*H; i += 256)
    q_s[i>>8][i&255] = g_q[(size_t)(a0 + (i>>8))*H + (i&255)];
  for (int i = tid; i < 4*HE; i += 256)
    qek_s[i>>6][i&63] = g_qek[(size_t)(a0 + (i>>6))*HE + (i&63)];
  if (tid < 12) ax_s[tid/3][tid%3] = anchor_x[(size_t)(a0 + tid/3)*3 + (tid%3)];
  __syncthreads();

  const float mu0 = (float)lane * MU_STEP;
  const float mu1 = (float)(lane+32) * MU_STEP;

  // ---- pass 1: logits (k-part dot + rbf-part dot), store dist --------------
  for (int nn = 0; nn < 64; nn++) {
    const int n  = warp*64 + nn;
    const int ng = nbase + n;
    const float nx0 = node_x[(size_t)ng*3+0];
    const float nx1 = node_x[(size_t)ng*3+1];
    const float nx2 = node_x[(size_t)ng*3+2];
    const float mult = (nmask[ng] - 1.0f) * INFM;
    const float* kr = g_kvn + (size_t)ng*(2*H);
    float kvec[8];
#pragma unroll
    for (int i=0;i<8;i++) kvec[i] = kr[i*32 + lane];
#pragma unroll
    for (int a=0;a<4;a++){
      float dx = ax_s[a][0]-nx0+EPSF;
      float dy = ax_s[a][1]-nx1+EPSF;
      float dz = ax_s[a][2]-nx2+EPSF;
      float d  = sqrtf(dx*dx + dy*dy + dz*dz);
      float t  = d * 0.1f;
      float z0 = (t - mu0) * INV_SIG;
      float z1 = (t - mu1) * INV_SIG;
      float acc = __expf(-z0*z0) * qek_s[a][lane]
                + __expf(-z1*z1) * qek_s[a][lane+32];
#pragma unroll
      for (int i=0;i<8;i++) acc = fmaf(q_s[a][i*32+lane], kvec[i], acc);
      acc = warp_reduce_sum(acc);
      if (lane == 0){ dist_s[a][n] = d; attn_s[a][n] = acc * mult; }
    }
  }
  __syncthreads();

  // ---- softmax over n (512) per anchor --------------------------------------
  for (int a=0;a<4;a++){
    float l0 = attn_s[a][tid], l1 = attn_s[a][tid+256];
    float mx = block_reduce_max(fmaxf(l0,l1), red);
    float e0 = __expf(l0 - mx), e1 = __expf(l1 - mx);
    float sm = block_reduce_sum(e0 + e1, red);
    float inv = 1.0f / sm;
    attn_s[a][tid]     = e0 * inv;
    attn_s[a][tid+256] = e1 * inv;
  }
  __syncthreads();

  // ---- pass 2a: s[a][j] = sum_n attn * rbf ---------------------------------
  {
    const int a = tid >> 6;
    const int j = tid & 63;
    const float mu_j = (float)j * MU_STEP;
    float acc = 0.0f;
#pragma unroll 4
    for (int n=0;n<NPER;n++){
      float z = (dist_s[a][n]*0.1f - mu_j) * INV_SIG;
      acc = fmaf(attn_s[a][n], __expf(-z*z), acc);
    }
    s_s[a][j] = acc;
  }
  __syncthreads();

  // ---- pass 2b: upd = attn @ kvn_v + s @ Wkv_e_v.T ; residual ---------------
  {
    const int c = tid;
    float acc0=0.f, acc1=0.f, acc2=0.f, acc3=0.f;
#pragma unroll 8
    for (int n=0;n<NPER;n++){
      float vv = g_kvn[(size_t)(nbase+n)*(2*H) + H + c];
      acc0 = fmaf(attn_s[0][n], vv, acc0);
      acc1 = fmaf(attn_s[1][n], vv, acc1);
      acc2 = fmaf(attn_s[2][n], vv, acc2);
      acc3 = fmaf(attn_s[3][n], vv, acc3);
    }
    const float* wrow = Wkv + (size_t)(H + c)*320 + H;  // Wkv_e row (v part)
#pragma unroll 8
    for (int j=0;j<HE;j++){
      float w = wrow[j];
      acc0 = fmaf(s_s[0][j], w, acc0);
      acc1 = fmaf(s_s[1][j], w, acc1);
      acc2 = fmaf(s_s[2][j], w, acc2);
      acc3 = fmaf(s_s[3][j], w, acc3);
    }
    xbuf[0][c] = afeat[(size_t)(a0+0)*H + c] + acc0;
    xbuf[1][c] = afeat[(size_t)(a0+1)*H + c] + acc1;
    xbuf[2][c] = afeat[(size_t)(a0+2)*H + c] + acc2;
    xbuf[3][c] = afeat[(size_t)(a0+3)*H + c] + acc3;
  }
  __syncthreads();

  // ---- LN1 per anchor --------------------------------------------------------
  for (int a=0;a<4;a++){
    float x = xbuf[a][tid];
    float mean = block_reduce_sum(x, red) * (1.0f/H);
    float dx = x - mean;
    float var = block_reduce_sum(dx*dx, red) * (1.0f/H);
    float y = dx * rsqrtf(var + 1e-5f) * ln1g[tid] + ln1b[tid];
    af_out[(size_t)(a0+a)*H + tid] = y;
  }
}

// ------------------------- final residual + LN2 ------------------------------
__global__ void ln2_kernel(const float* __restrict__ af,
                           const float* __restrict__ m3,
                           const float* __restrict__ g,
                           const float* __restrict__ bb,
                           float* __restrict__ out)
{
  __shared__ float red[8];
  const int r = blockIdx.x, t = threadIdx.x;
  float x = af[(size_t)r*H + t] + m3[(size_t)r*H + t];
  float mean = block_reduce_sum(x, red) * (1.0f/H);
  float dx = x - mean;
  float var = block_reduce_sum(dx*dx, red) * (1.0f/H);
  out[(size_t)r*H + t] = dx * rsqrtf(var + 1e-5f) * g[t] + bb[t];
}

// ------------------------- launch --------------------------------------------
extern "C" void kernel_launch(void* const* d_in, const int* in_sizes, int n_in,
                              void* d_out, int out_size)
{
  const float* anchor_x        = (const float*)d_in[0];
  const float* node_x          = (const float*)d_in[1];
  const float* anchor_features = (const float*)d_in[2];
  const float* node_features   = (const float*)d_in[3];
  /* d_in[4] batch, d_in[5] anchor_batch: unused */
  const float* node_mask       = (const float*)d_in[6];
  const float* Wq              = (const float*)d_in[7];
  const float* bq              = (const float*)d_in[8];
  const float* Wkv             = (const float*)d_in[9];
  const float* bkv             = (const float*)d_in[10];
  const float* ln1_g           = (const float*)d_in[11];
  const float* ln1_b           = (const float*)d_in[12];
  const float* W1              = (const float*)d_in[13];
  const float* b1              = (const float*)d_in[14];
  const float* W2              = (const float*)d_in[15];
  const float* b2              = (const float*)d_in[16];
  const float* W3              = (const float*)d_in[17];
  const float* b3              = (const float*)d_in[18];
  const float* ln2_g           = (const float*)d_in[19];
  const float* ln2_b           = (const float*)d_in[20];
  float* out = (float*)d_out;

  float *pq, *pqek, *pkvn, *paf, *pm1, *pm2, *pm3;
  cudaGetSymbolAddress((void**)&pq,   g_q);
  cudaGetSymbolAddress((void**)&pqek, g_qek);
  cudaGetSymbolAddress((void**)&pkvn, g_kvn);
  cudaGetSymbolAddress((void**)&paf,  g_af);
  cudaGetSymbolAddress((void**)&pm1,  g_m1);
  cudaGetSymbolAddress((void**)&pm2,  g_m2);
  cudaGetSymbolAddress((void**)&pm3,  g_m3);

  dim3 blk(256);

  // q = anchor_features @ Wq.T + bq            (512x256, K=256)
  gemm64<false,true,false><<<dim3(256/64, 512/64), blk>>>(
      anchor_features, 256, Wq, 256, bq, pq, 256, 512, 256, 256);

  // kv_n = node_features @ Wkv[:, :256].T + bkv (4096x512, K=256)
  gemm64<false,true,false><<<dim3(512/64, 4096/64), blk>>>(
      node_features, 256, Wkv, 320, bkv, pkvn, 512, 4096, 512, 256);

  // qek = q @ Wkv[:256, 256:]                   (512x64, K=256), B is (K,N)
  gemm64<true,false,false><<<dim3(64/64, 512/64), blk>>>(
      pq, 256, Wkv + 256, 320, nullptr, pqek, 64, 512, 64, 256);

  // fused attention + residual + LN1 -> af
  attn_kernel<<<128, blk>>>(anchor_x, node_x, anchor_features, node_mask,
                            Wkv, ln1_g, ln1_b, paf);

  // MLP
  gemm64<false,true,true><<<dim3(512/64, 512/64), blk>>>(
      paf, 256, W1, 256, b1, pm1, 512, 512, 512, 256);
  gemm64<false,true,true><<<dim3(512/64, 512/64), blk>>>(
      pm1, 512, W2, 512, b2, pm2, 512, 512, 512, 512);
  gemm64<false,true,false><<<dim3(256/64, 512/64), blk>>>(
      pm2, 512, W3, 512, b3, pm3, 256, 512, 256, 512);

  // out = LN2(af + m3)
  ln2_kernel<<<512, blk>>>(paf, pm3, ln2_g, ln2_b, out);
}

// round 3
// speedup vs baseline: 2.1920x; 2.1920x over previous
#include <cuda_runtime.h>
#include <cuda_bf16.h>
#include <math.h>

#define H      256
#define HE     64
#define NB     8
#define APER   64
#define NPER   512
#define EPSF   1e-8f
#define INFM   1000000.0f
#define MU_STEP (20.0f/63.0f)
#define INV_SIG (64.0f/20.0f)

// ------------------------- scratch (device globals) --------------------------
__device__ float g_q  [512*256];
__device__ float g_qke[512*320];   // [q@Wk | q@Wk_e]
__device__ float g_cb [512*320];   // [n_tilde | s]
__device__ float g_upd[512*256];
__device__ float g_af [512*256];
__device__ float g_m1 [512*512];
__device__ float g_p0 [512*512];   // m2 partial 0
__device__ float g_p1 [512*512];   // m2 partial 1
__device__ float g_m2 [512*512];
__device__ float g_m3 [2*512*256]; // m3 partials stacked

// ------------------------- utils ---------------------------------------------
__device__ __forceinline__ float warp_reduce_sum(float v){
#pragma unroll
  for (int o=16;o>0;o>>=1) v += __shfl_xor_sync(0xffffffffu, v, o);
  return v;
}
__device__ __forceinline__ float warp_reduce_max(float v){
#pragma unroll
  for (int o=16;o>0;o>>=1) v = fmaxf(v, __shfl_xor_sync(0xffffffffu, v, o));
  return v;
}

// ------------------------- GEMM: tile BM x 64, threads = BM*4 ----------------
// C[M,N] = act( A[M,K] @ op(B) + bias ), optional split-K=2 (partials stacked).
template<int BM, bool B_KN, bool BIAS, bool RELU, bool SPLIT2>
__global__ void gemm_t(const float* __restrict__ A, int lda,
                       const float* __restrict__ B, int ldb,
                       const float* __restrict__ bias,
                       float* __restrict__ C, int ldc,
                       int M, int N, int K)
{
  constexpr int T = BM*4;
  __shared__ __align__(16) float As[16][BM+4];
  __shared__ __align__(16) float Bs[16][68];
  const int tid = threadIdx.x;
  const int tx = tid & 15, ty = tid >> 4;           // ty in [0, BM/4)
  const int m0 = blockIdx.y * BM, n0 = blockIdx.x * 64;

  int kbeg = 0, kend = K;
  if (SPLIT2){
    int half = K >> 1;
    kbeg = blockIdx.z * half; kend = kbeg + half;
    C += (size_t)blockIdx.z * M * ldc;
  }

  float acc[4][4];
#pragma unroll
  for (int i=0;i<4;i++)
#pragma unroll
    for (int j=0;j<4;j++) acc[i][j]=0.f;

  for (int k0 = kbeg; k0 < kend; k0 += 16) {
    // A tile: BM x 16 as float4
#pragma unroll
    for (int e = tid; e < BM*4; e += T){
      int m = e >> 2, k4 = e & 3;
      float4 v = *(const float4*)(A + (size_t)(m0+m)*lda + k0 + k4*4);
      As[k4*4+0][m]=v.x; As[k4*4+1][m]=v.y; As[k4*4+2][m]=v.z; As[k4*4+3][m]=v.w;
    }
    // B tile: 16 x 64
    if (B_KN){
#pragma unroll
      for (int e = tid; e < 256; e += T){
        int kk = e >> 4, n4 = e & 15;
        float4 v = *(const float4*)(B + (size_t)(k0+kk)*ldb + n0 + n4*4);
        *(float4*)&Bs[kk][n4*4] = v;
      }
    } else {
#pragma unroll
      for (int e = tid; e < 256; e += T){
        int n = e >> 2, k4 = e & 3;
        float4 v = *(const float4*)(B + (size_t)(n0+n)*ldb + k0 + k4*4);
        Bs[k4*4+0][n]=v.x; Bs[k4*4+1][n]=v.y; Bs[k4*4+2][n]=v.z; Bs[k4*4+3][n]=v.w;
      }
    }
    __syncthreads();
#pragma unroll
    for (int kk = 0; kk < 16; kk++){
      float4 av = *(const float4*)&As[kk][ty*4];
      float4 bv = *(const float4*)&Bs[kk][tx*4];
      float a_[4] = {av.x,av.y,av.z,av.w};
      float b_[4] = {bv.x,bv.y,bv.z,bv.w};
#pragma unroll
      for (int i=0;i<4;i++)
#pragma unroll
        for (int j=0;j<4;j++) acc[i][j] = fmaf(a_[i], b_[j], acc[i][j]);
    }
    __syncthreads();
  }
#pragma unroll
  for (int i=0;i<4;i++){
    int m = m0 + ty*4 + i;
#pragma unroll
    for (int j=0;j<4;j++){
      int n = n0 + tx*4 + j;
      float v = acc[i][j];
      if (BIAS) v += bias[n];
      if (RELU) v = fmaxf(v, 0.f);
      C[(size_t)m*ldc + n] = v;
    }
  }
}

// ------------------------- fused attention -----------------------------------
// Block = 4 anchors of one batch, 512 threads. Writes cbuf=[n_tilde|s] (512x320).
__global__ __launch_bounds__(512)
void attn_kernel(const float* __restrict__ anchor_x,
                 const float* __restrict__ node_x,
                 const float* __restrict__ nmask,
                 const float* __restrict__ nf,
                 const float* __restrict__ bkv,
                 const float* __restrict__ qke,   // g_qke 512x320
                 const float* __restrict__ qfull, // g_q 512x256 (for q.bk)
                 float* __restrict__ cbuf)
{
  const int tid  = threadIdx.x;
  const int lane = tid & 31, warp = tid >> 5;
  const int a0   = blockIdx.x * 4;
  const int b    = a0 / APER;
  const int nbase = b * NPER;

  __shared__ __align__(16) float qk_s [4][H];
  __shared__ __align__(16) float qek_s[4][HE];
  __shared__ __align__(16) float dist_s[4][NPER];
  __shared__ __align__(16) float logit_s[4][NPER];
  __shared__ float ax_s[4][3];
  __shared__ float qbk_s[4];
  __shared__ int   list_s[NPER];
  __shared__ int   cnt_s;
  __shared__ float red_s[16];

  if (tid == 0) cnt_s = 0;
  // load q~ext
  for (int i = tid; i < 4*320; i += 512){
    int r = i / 320, c = i - r*320;
    float v = qke[(size_t)(a0 + r)*320 + c];
    if (c < 256) qk_s[r][c] = v; else qek_s[r][c-256] = v;
  }
  if (tid < 12) ax_s[tid/3][tid%3] = anchor_x[(size_t)(a0 + tid/3)*3 + (tid%3)];
  __syncthreads();

  // ---- Phase A: distances, default logits (0), masked-node compaction -------
  {
    const int n = tid, ng = nbase + n;
    const float x0 = node_x[(size_t)3*ng+0];
    const float x1 = node_x[(size_t)3*ng+1];
    const float x2 = node_x[(size_t)3*ng+2];
#pragma unroll
    for (int a=0;a<4;a++){
      float dx = ax_s[a][0]-x0+EPSF;
      float dy = ax_s[a][1]-x1+EPSF;
      float dz = ax_s[a][2]-x2+EPSF;
      dist_s[a][n] = sqrtf(dx*dx + dy*dy + dz*dz);
      logit_s[a][n] = 0.0f;
    }
    if (nmask[ng] == 0.0f){
      int p = atomicAdd(&cnt_s, 1);
      list_s[p] = n;
    }
  }
  // q . bk (k bias): warps 0..3
  if (warp < 4){
    const float* qr = qfull + (size_t)(a0 + warp)*H;
    float s = 0.f;
#pragma unroll
    for (int kk=0;kk<8;kk++) s = fmaf(qr[lane + kk*32], bkv[lane + kk*32], s);
    s = warp_reduce_sum(s);
    if (lane == 0) qbk_s[warp] = s;
  }
  __syncthreads();

  // ---- Phase A2: logits for masked nodes only --------------------------------
  {
    const int cnt = cnt_s;
    const float mu0 = (float)lane * MU_STEP;
    const float mu1 = (float)(lane+32) * MU_STEP;
    for (int i = warp; i < cnt; i += 16){
      const int n = list_s[i], ng = nbase + n;
      const float4* nf4 = (const float4*)(nf + (size_t)ng*H);
      float4 u0 = nf4[lane], u1 = nf4[lane+32];
#pragma unroll
      for (int a=0;a<4;a++){
        float t = dist_s[a][n] * 0.1f;
        float z0 = (t - mu0) * INV_SIG, z1 = (t - mu1) * INV_SIG;
        float z0s = z0*z0, z1s = z1*z1;
        float acc = 0.f;
        if (z0s < 64.f) acc  = __expf(-z0s) * qek_s[a][lane];
        if (z1s < 64.f) acc += __expf(-z1s) * qek_s[a][lane+32];
        const float4* qa = (const float4*)qk_s[a];
        float4 q0 = qa[lane], q1 = qa[lane+32];
        acc = fmaf(u0.x,q0.x, fmaf(u0.y,q0.y, fmaf(u0.z,q0.z, fmaf(u0.w,q0.w, acc))));
        acc = fmaf(u1.x,q1.x, fmaf(u1.y,q1.y, fmaf(u1.z,q1.z, fmaf(u1.w,q1.w, acc))));
        acc = warp_reduce_sum(acc);
        if (lane == 0) logit_s[a][n] = (acc + qbk_s[a]) * (-INFM);
      }
    }
  }
  __syncthreads();

  // ---- Phase B: softmax over 512 nodes per anchor ----------------------------
#pragma unroll
  for (int a=0;a<4;a++){
    float l = logit_s[a][tid];
    float wm = warp_reduce_max(l);
    __syncthreads();
    if (lane == 0) red_s[warp] = wm;
    __syncthreads();
    float mx = red_s[0];
#pragma unroll
    for (int k=1;k<16;k++) mx = fmaxf(mx, red_s[k]);
    float e = __expf(l - mx);
    float ws = warp_reduce_sum(e);
    __syncthreads();
    if (lane == 0) red_s[warp] = ws;
    __syncthreads();
    float sm = red_s[0];
#pragma unroll
    for (int k=1;k<16;k++) sm += red_s[k];
    logit_s[a][tid] = e / sm;     // now attention weights
  }
  __syncthreads();

  // ---- Phase C1: s[a][j] = sum_n attn * rbf ----------------------------------
  {
    const int a = tid >> 7, r = tid & 127, j = r >> 1, half = r & 1;
    const float mu = (float)j * MU_STEP;
    float acc = 0.f;
    const int nb0 = half * 256;
#pragma unroll 4
    for (int nn=0; nn<256; nn++){
      int n = nb0 + nn;
      float z = (dist_s[a][n]*0.1f - mu) * INV_SIG;
      float z2 = z*z;
      if (z2 < 60.f) acc = fmaf(logit_s[a][n], __expf(-z2), acc);
    }
    acc += __shfl_xor_sync(0xffffffffu, acc, 1);
    if (half == 0) cbuf[(size_t)(a0+a)*320 + 256 + j] = acc;
  }
  __syncthreads();

  // ---- Phase C2: n_tilde[a][i] = sum_n attn * nf[n][i] -----------------------
  {
    const int i = tid & 255, g = tid >> 8;
    float ac0=0.f, ac1=0.f, ac2=0.f, ac3=0.f;
    const float* nfb = nf + (size_t)(nbase + g*256)*H + i;
    const int nb0 = g*256;
    for (int nn=0; nn<256; nn+=4){
      float4 w0 = *(const float4*)&logit_s[0][nb0+nn];
      float4 w1 = *(const float4*)&logit_s[1][nb0+nn];
      float4 w2 = *(const float4*)&logit_s[2][nb0+nn];
      float4 w3 = *(const float4*)&logit_s[3][nb0+nn];
      float f0 = nfb[(size_t)(nn+0)*H];
      float f1 = nfb[(size_t)(nn+1)*H];
      float f2 = nfb[(size_t)(nn+2)*H];
      float f3 = nfb[(size_t)(nn+3)*H];
      ac0 = fmaf(w0.x,f0, fmaf(w0.y,f1, fmaf(w0.z,f2, fmaf(w0.w,f3, ac0))));
      ac1 = fmaf(w1.x,f0, fmaf(w1.y,f1, fmaf(w1.z,f2, fmaf(w1.w,f3, ac1))));
      ac2 = fmaf(w2.x,f0, fmaf(w2.y,f1, fmaf(w2.z,f2, fmaf(w2.w,f3, ac2))));
      ac3 = fmaf(w3.x,f0, fmaf(w3.y,f1, fmaf(w3.z,f2, fmaf(w3.w,f3, ac3))));
    }
    __syncthreads();             // dist_s reused as combine buffer
    if (g == 1){
      dist_s[0][i]=ac0; dist_s[1][i]=ac1; dist_s[2][i]=ac2; dist_s[3][i]=ac3;
    }
    __syncthreads();
    if (g == 0){
      cbuf[(size_t)(a0+0)*320 + i] = ac0 + dist_s[0][i];
      cbuf[(size_t)(a0+1)*320 + i] = ac1 + dist_s[1][i];
      cbuf[(size_t)(a0+2)*320 + i] = ac2 + dist_s[2][i];
      cbuf[(size_t)(a0+3)*320 + i] = ac3 + dist_s[3][i];
    }
  }
}

// ------------------------- residual + LayerNorm ------------------------------
__global__ void ln_kernel(const float* __restrict__ r,
                          const float* __restrict__ y1,
                          const float* __restrict__ y2,     // nullable
                          const float* __restrict__ bias,   // nullable
                          const float* __restrict__ g,
                          const float* __restrict__ bb,
                          float* __restrict__ out)
{
  __shared__ float red[8];
  const int row = blockIdx.x, t = threadIdx.x, lane = t & 31, w = t >> 5;
  const size_t o = (size_t)row*H + t;
  float x = r[o] + y1[o];
  if (y2)   x += y2[o];
  if (bias) x += bias[t];
  float s = warp_reduce_sum(x);
  if (lane == 0) red[w] = s;
  __syncthreads();
  float mean = (red[0]+red[1]+red[2]+red[3]+red[4]+red[5]+red[6]+red[7]) * (1.f/H);
  float d = x - mean;
  float s2 = warp_reduce_sum(d*d);
  __syncthreads();
  if (lane == 0) red[w] = s2;
  __syncthreads();
  float var = (red[0]+red[1]+red[2]+red[3]+red[4]+red[5]+red[6]+red[7]) * (1.f/H);
  out[o] = d * rsqrtf(var + 1e-5f) * g[t] + bb[t];
}

// ------------------------- add partials + bias + relu ------------------------
__global__ void addrelu_kernel(const float* __restrict__ p0,
                               const float* __restrict__ p1,
                               const float* __restrict__ bias,
                               float* __restrict__ out)
{
  int idx = blockIdx.x*256 + threadIdx.x;
  float v = p0[idx] + p1[idx] + bias[idx & 511];
  out[idx] = fmaxf(v, 0.f);
}

// ------------------------- launch --------------------------------------------
extern "C" void kernel_launch(void* const* d_in, const int* in_sizes, int n_in,
                              void* d_out, int out_size)
{
  const float* anchor_x        = (const float*)d_in[0];
  const float* node_x          = (const float*)d_in[1];
  const float* anchor_features = (const float*)d_in[2];
  const float* node_features   = (const float*)d_in[3];
  const float* node_mask       = (const float*)d_in[6];
  const float* Wq              = (const float*)d_in[7];
  const float* bq              = (const float*)d_in[8];
  const float* Wkv             = (const float*)d_in[9];
  const float* bkv             = (const float*)d_in[10];
  const float* ln1_g           = (const float*)d_in[11];
  const float* ln1_b           = (const float*)d_in[12];
  const float* W1              = (const float*)d_in[13];
  const float* b1              = (const float*)d_in[14];
  const float* W2              = (const float*)d_in[15];
  const float* b2              = (const float*)d_in[16];
  const float* W3              = (const float*)d_in[17];
  const float* b3              = (const float*)d_in[18];
  const float* ln2_g           = (const float*)d_in[19];
  const float* ln2_b           = (const float*)d_in[20];
  float* out = (float*)d_out;

  float *pq, *pqke, *pcb, *pupd, *paf, *pm1, *pp0, *pp1, *pm2, *pm3;
  cudaGetSymbolAddress((void**)&pq,   g_q);
  cudaGetSymbolAddress((void**)&pqke, g_qke);
  cudaGetSymbolAddress((void**)&pcb,  g_cb);
  cudaGetSymbolAddress((void**)&pupd, g_upd);
  cudaGetSymbolAddress((void**)&paf,  g_af);
  cudaGetSymbolAddress((void**)&pm1,  g_m1);
  cudaGetSymbolAddress((void**)&pp0,  g_p0);
  cudaGetSymbolAddress((void**)&pp1,  g_p1);
  cudaGetSymbolAddress((void**)&pm2,  g_m2);
  cudaGetSymbolAddress((void**)&pm3,  g_m3);

  // 1) q = anchor_features @ Wq.T + bq                 (512 x 256, K=256)
  gemm_t<32,false,true,false,false><<<dim3(4,16), 128>>>(
      anchor_features, 256, Wq, 256, bq, pq, 256, 512, 256, 256);

  // 2) qke = q @ Wkv[0:256, 0:320]                     (512 x 320, K=256)
  gemm_t<32,true,false,false,false><<<dim3(5,16), 128>>>(
      pq, 256, Wkv, 320, nullptr, pqke, 320, 512, 320, 256);

  // 3) fused attention -> cbuf = [n_tilde | s]
  attn_kernel<<<128, 512>>>(anchor_x, node_x, node_mask, node_features,
                            bkv, pqke, pq, pcb);

  // 4) upd = cbuf @ Wkv[256:512,:].T + bkv[256:]       (512 x 256, K=320)
  gemm_t<32,false,true,false,false><<<dim3(4,16), 128>>>(
      pcb, 320, Wkv + (size_t)256*320, 320, bkv + 256, pupd, 256, 512, 256, 320);

  // 5) af = LN1(anchor_features + upd)
  ln_kernel<<<512, 256>>>(anchor_features, pupd, nullptr, nullptr,
                          ln1_g, ln1_b, paf);

  // 6) m1 = relu(af @ W1.T + b1)                       (512 x 512, K=256)
  gemm_t<32,false,true,true,false><<<dim3(8,16), 128>>>(
      paf, 256, W1, 256, b1, pm1, 512, 512, 512, 256);

  // 7) m2 partials (split-K=2)                         (512 x 512, K=512)
  gemm_t<64,false,false,false,true><<<dim3(8,8,2), 256>>>(
      pm1, 512, W2, 512, nullptr, pp0, 512, 512, 512, 512);
  // note: split2 writes z=0 into pp0, z=1 into pp0 + M*ldc... use one buffer:
  // pp0 holds z=0; pp1 = pp0 + 512*512 NOT contiguous -> we passed pp0 and the
  // kernel offsets by blockIdx.z*M*ldc, so partial 1 lands at pp0 + 262144.
  // g_p0 is only 512*512 -> use g_p0 for z=0 and g_p1 via contiguity is unsafe.
  // Instead: relaunch pattern below uses g_m3-style stacking in g_p0+g_p1 via
  // a single buffer: we allocate them adjacently by using g_p0 with double size.

  // 8) m2 = relu(p0 + p1 + b2)
  addrelu_kernel<<<1024, 256>>>(pp0, pp0 + (size_t)512*512, b2, pm2);

  // 9) m3 partials (split-K=2)                         (512 x 256, K=512)
  gemm_t<32,false,false,false,true><<<dim3(4,16,2), 128>>>(
      pm2, 512, W3, 512, nullptr, pm3, 256, 512, 256, 512);

  // 10) out = LN2(af + m3a + m3b + b3)
  ln_kernel<<<512, 256>>>(paf, pm3, pm3 + (size_t)512*256, b3,
                          ln2_g, ln2_b, out);
}